// round 7
// baseline (speedup 1.0000x reference)
#include <cuda_runtime.h>
#include <cuda_bf16.h>
#include <cstdint>

#define NPIX (512*512)
#define CZ 128
#define CT 64
#define NTPL 4
#define NH 4
#define DH 32

// ---------------- device scratch: combined weights, bf16 hi/lo, [n][k] row-major ----
__device__ __align__(256) __nv_bfloat16 g_W1h[2 * 128 * 128];  // [nh][n][kz]
__device__ __align__(256) __nv_bfloat16 g_W1l[2 * 128 * 128];
__device__ __align__(256) __nv_bfloat16 g_W2h[128 * 256];      // [n][kk]
__device__ __align__(256) __nv_bfloat16 g_W2l[128 * 256];

// ---------------- helpers ----------------
__device__ __forceinline__ uint32_t smem_u32(const void* p) {
    uint32_t a;
    asm("{ .reg .u64 t; cvta.to.shared.u64 t, %1; cvt.u32.u64 %0, t; }" : "=r"(a) : "l"(p));
    return a;
}
__device__ __forceinline__ void ldx4(uint32_t r[4], uint32_t addr) {
    asm volatile("ldmatrix.sync.aligned.m8n8.x4.shared.b16 {%0,%1,%2,%3}, [%4];"
                 : "=r"(r[0]), "=r"(r[1]), "=r"(r[2]), "=r"(r[3]) : "r"(addr));
}
__device__ __forceinline__ void mma16816(float c[4], const uint32_t a[4],
                                         uint32_t b0, uint32_t b1) {
    asm volatile(
        "mma.sync.aligned.m16n8k16.row.col.f32.bf16.bf16.f32 "
        "{%0,%1,%2,%3}, {%4,%5,%6,%7}, {%8,%9}, {%0,%1,%2,%3};"
        : "+f"(c[0]), "+f"(c[1]), "+f"(c[2]), "+f"(c[3])
        : "r"(a[0]), "r"(a[1]), "r"(a[2]), "r"(a[3]), "r"(b0), "r"(b1));
}
__device__ __forceinline__ uint32_t pack_bf2(float x, float y) {
    __nv_bfloat162 p = __halves2bfloat162(__float2bfloat16(x), __float2bfloat16(y));
    return *(uint32_t*)&p;
}
__device__ __forceinline__ void cp16(uint32_t dst, const void* src) {
    asm volatile("cp.async.cg.shared.global [%0], [%1], 16;" :: "r"(dst), "l"(src));
}
__device__ __forceinline__ void cp_commit() { asm volatile("cp.async.commit_group;"); }
__device__ __forceinline__ void cp_wait0() {
    asm volatile("cp.async.wait_group 0;" ::: "memory");
}

// ---------------- prep: combined weights, bf16 hi/lo split ----------------
__global__ void prep_kernel(const float* __restrict__ wq, const float* __restrict__ wk,
                            const float* __restrict__ wv, const float* __restrict__ wo) {
    int id = blockIdx.x * blockDim.x + threadIdx.x;
    float val;
    __nv_bfloat16 *dh, *dl;
    int idx;
    if (id < 32768) {
        int kz = id & 127, n = (id >> 7) & 127, nh = id >> 14;
        int hc = nh * 128 + n;
        int h = hc >> 6, c = hc & 63;
        float s = 0.f;
#pragma unroll
        for (int dd = 0; dd < DH; ++dd)
            s += wq[kz * CZ + h * DH + dd] * wk[c * CZ + h * DH + dd];
        val = s * 0.17677669529663687f;
        dh = g_W1h; dl = g_W1l; idx = id;
    } else {
        int e = id - 32768;
        int kk = e & 255, n = e >> 8;
        int h = kk >> 6, c = kk & 63;
        float s = 0.f;
#pragma unroll
        for (int dd = 0; dd < DH; ++dd)
            s += wv[c * CZ + h * DH + dd] * wo[(h * DH + dd) * CZ + n];
        val = s;
        dh = g_W2h; dl = g_W2l; idx = e;
    }
    __nv_bfloat16 hi = __float2bfloat16(val);
    __nv_bfloat16 lo = __float2bfloat16(val - __bfloat162float(hi));
    dh[idx] = hi;
    dl[idx] = lo;
}

// ---------------- smem layout (bytes) ----------------
// Zhi [128][272B]  @ 0       (34816)
// Zlo             @ 34816    (34816)
// U fp32 [128][512B] / { Mhi [128][272B], Mlo } @ 69632 (69632)
// Wbuf 4 x 10240  @ 139264   (40960)   total 180224
static constexpr int OFF_ZLO = 34816;
static constexpr int OFF_UM = 69632;
static constexpr int OFF_MLO = 104448;
static constexpr int OFF_W = 139264;
static constexpr int FSMEM = 180224;

// ---------------- GEMM phase: acc += A(smem,3-term split) @ W(gmem streamed) ----------
// A planes pitch 272B, K=128 (4 chunks of 32). W row pitch wpitch halves, chunk at
// kofs + kt*32. 16 warps, warp tile 32x32 (mw,nw in 0..3), acc[2][4][4].
__device__ __forceinline__ void gemm_phase(
    uint32_t aHi, uint32_t aLo,
    const __nv_bfloat16* __restrict__ Wh, const __nv_bfloat16* __restrict__ Wl,
    int wpitch, int kofs, uint32_t wbuf,
    float acc[2][4][4], int tid, int lane, int mw, int nw) {
    const int lrow = lane & 15;
    const int lkb = (lane >> 4) * 16;
    auto issue = [&](int kt, int s) {
#pragma unroll
        for (int i = 0; i < 2; ++i) {
            int id = tid + 512 * i;
            int plane = id >> 9;
            int r = (id >> 2) & 127;
            int c = id & 3;
            const __nv_bfloat16* src =
                (plane ? Wl : Wh) + (size_t)r * wpitch + kofs + kt * 32 + c * 8;
            cp16(wbuf + (uint32_t)((s * 2 + plane) * 10240 + r * 80 + c * 16), src);
        }
        cp_commit();
    };
    issue(0, 0);
#pragma unroll 1
    for (int kt = 0; kt < 4; ++kt) {
        const int s = kt & 1;
        cp_wait0();
        __syncthreads();
        if (kt < 3) issue(kt + 1, s ^ 1);
        const uint32_t wH = wbuf + (uint32_t)(s * 2) * 10240;
        const uint32_t wL = wH + 10240;
#pragma unroll
        for (int k16 = 0; k16 < 2; ++k16) {
            const uint32_t kbA = (uint32_t)(kt * 64 + k16 * 32 + lkb);
            const uint32_t kbW = (uint32_t)(k16 * 32 + lkb);
            uint32_t bh[2][4], bl[2][4];
#pragma unroll
            for (int ng = 0; ng < 2; ++ng) {
                uint32_t off = (uint32_t)(nw * 32 + ng * 16 + lrow) * 80 + kbW;
                ldx4(bh[ng], wH + off);
                ldx4(bl[ng], wL + off);
            }
#pragma unroll
            for (int mb = 0; mb < 2; ++mb) {
                uint32_t roff = (uint32_t)(mw * 32 + mb * 16 + lrow) * 272 + kbA;
                uint32_t ah[4], al[4];
                ldx4(ah, aHi + roff);
                ldx4(al, aLo + roff);
#pragma unroll
                for (int nb = 0; nb < 4; ++nb) {
                    const int ng = nb >> 1, hf = nb & 1;
                    mma16816(acc[mb][nb], ah, bh[ng][hf], bh[ng][2 + hf]);
                    mma16816(acc[mb][nb], ah, bl[ng][hf], bl[ng][2 + hf]);
                    mma16816(acc[mb][nb], al, bh[ng][hf], bh[ng][2 + hf]);
                }
            }
        }
        __syncthreads();
    }
}

// ---------------- fused kernel: z -> U -> attn -> M -> out, per 128-pixel tile -------
__global__ __launch_bounds__(512, 1) void fused_kernel(
    const float* __restrict__ t, const float* __restrict__ z,
    const float* __restrict__ mask, const float* __restrict__ bo,
    float* __restrict__ out) {
    extern __shared__ char sm[];
    const uint32_t sb = smem_u32(sm);
    const int tid = threadIdx.x;
    const int lane = tid & 31;
    const int wid = tid >> 5;
    const int mw = wid & 3, nw = wid >> 2;
    const int pb = blockIdx.x * 128;

    const uint32_t ZHI = sb, ZLO = sb + OFF_ZLO;
    const uint32_t MHI = sb + OFF_UM, MLO = sb + OFF_MLO;
    const uint32_t WBUF = sb + OFF_W;
    float* const Usm = (float*)(sm + OFF_UM);

    // ---- load z tile, split to hi/lo bf16 planes (pitch 272B) ----
#pragma unroll
    for (int i = 0; i < 8; ++i) {
        int idx = tid + 512 * i;
        int r = idx >> 5, q = idx & 31;
        float4 v = __ldg((const float4*)(z + (size_t)(pb + r) * 128 + q * 4));
        __nv_bfloat16 h0 = __float2bfloat16(v.x), h1 = __float2bfloat16(v.y);
        __nv_bfloat16 h2 = __float2bfloat16(v.z), h3 = __float2bfloat16(v.w);
        uint2 ph, pl;
        ph.x = pack_bf2(v.x, v.y); ph.y = pack_bf2(v.z, v.w);
        pl.x = pack_bf2(v.x - __bfloat162float(h0), v.y - __bfloat162float(h1));
        pl.y = pack_bf2(v.z - __bfloat162float(h2), v.w - __bfloat162float(h3));
        *(uint2*)(sm + r * 272 + q * 8) = ph;
        *(uint2*)(sm + OFF_ZLO + r * 272 + q * 8) = pl;
    }
    float mbias[NTPL];
#pragma unroll
    for (int nt = 0; nt < NTPL; ++nt)
        mbias[nt] = 100000.0f * (__ldg(mask + nt) - 1.0f);
    __syncthreads();

    float outacc[2][4][4];
#pragma unroll
    for (int i = 0; i < 2; ++i)
#pragma unroll
        for (int j = 0; j < 4; ++j)
#pragma unroll
            for (int q = 0; q < 4; ++q) outacc[i][j][q] = 0.f;

    const int r4 = lane >> 2, c2 = (lane & 3) * 2;

#pragma unroll 1
    for (int nh = 0; nh < 2; ++nh) {
        // ---- GEMM1 half: U = Z @ W1[nh] ----
        float acc[2][4][4];
#pragma unroll
        for (int i = 0; i < 2; ++i)
#pragma unroll
            for (int j = 0; j < 4; ++j)
#pragma unroll
                for (int q = 0; q < 4; ++q) acc[i][j][q] = 0.f;
        gemm_phase(ZHI, ZLO, g_W1h + nh * 16384, g_W1l + nh * 16384, 128, 0,
                   WBUF, acc, tid, lane, mw, nw);

        // write U half to smem (fp32, pitch 128 floats)
#pragma unroll
        for (int mb = 0; mb < 2; ++mb)
#pragma unroll
            for (int nb = 0; nb < 4; ++nb) {
                int row = mw * 32 + mb * 16 + r4;
                int col = nw * 32 + nb * 8 + c2;
                *(float2*)(Usm + row * 128 + col) =
                    make_float2(acc[mb][nb][0], acc[mb][nb][1]);
                *(float2*)(Usm + (row + 8) * 128 + col) =
                    make_float2(acc[mb][nb][2], acc[mb][nb][3]);
            }
        __syncthreads();

        // ---- attention: warp-per-pixel, 8 pixels/warp ----
        float uh[8][2][2];
#pragma unroll
        for (int i = 0; i < 8; ++i) {
            int p = wid * 8 + i;
#pragma unroll
            for (int h2 = 0; h2 < 2; ++h2)
#pragma unroll
                for (int j = 0; j < 2; ++j)
                    uh[i][h2][j] = Usm[p * 128 + h2 * 64 + j * 32 + lane];
        }
        __syncthreads();  // U region now reusable as M

#pragma unroll 1
        for (int i = 0; i < 8; ++i) {
            int p = wid * 8 + i;
            float tt[NTPL][2];
#pragma unroll
            for (int nt = 0; nt < NTPL; ++nt)
#pragma unroll
                for (int j = 0; j < 2; ++j)
                    tt[nt][j] = __ldg(t + ((size_t)nt * NPIX + pb + p) * CT + j * 32 + lane);

            float lg[2][NTPL];
#pragma unroll
            for (int h2 = 0; h2 < 2; ++h2)
#pragma unroll
                for (int nt = 0; nt < NTPL; ++nt)
                    lg[h2][nt] = uh[i][h2][0] * tt[nt][0] + uh[i][h2][1] * tt[nt][1];
#pragma unroll
            for (int off = 16; off > 0; off >>= 1)
#pragma unroll
                for (int h2 = 0; h2 < 2; ++h2)
#pragma unroll
                    for (int nt = 0; nt < NTPL; ++nt)
                        lg[h2][nt] += __shfl_xor_sync(0xFFFFFFFFu, lg[h2][nt], off);

            float at[2][NTPL];
#pragma unroll
            for (int h2 = 0; h2 < 2; ++h2) {
                float l0 = lg[h2][0] + mbias[0], l1 = lg[h2][1] + mbias[1];
                float l2 = lg[h2][2] + mbias[2], l3 = lg[h2][3] + mbias[3];
                float mx = fmaxf(fmaxf(l0, l1), fmaxf(l2, l3));
                float e0 = __expf(l0 - mx), e1 = __expf(l1 - mx);
                float e2 = __expf(l2 - mx), e3 = __expf(l3 - mx);
                float inv = __fdividef(1.0f, e0 + e1 + e2 + e3);
                at[h2][0] = e0 * inv; at[h2][1] = e1 * inv;
                at[h2][2] = e2 * inv; at[h2][3] = e3 * inv;
            }
#pragma unroll
            for (int h2 = 0; h2 < 2; ++h2)
#pragma unroll
                for (int j = 0; j < 2; ++j) {
                    float m = at[h2][0] * tt[0][j] + at[h2][1] * tt[1][j] +
                              at[h2][2] * tt[2][j] + at[h2][3] * tt[3][j];
                    __nv_bfloat16 mh = __float2bfloat16(m);
                    __nv_bfloat16 ml = __float2bfloat16(m - __bfloat162float(mh));
                    int cofs = p * 272 + (h2 * 64 + j * 32 + lane) * 2;
                    *(__nv_bfloat16*)(sm + OFF_UM + cofs) = mh;
                    *(__nv_bfloat16*)(sm + OFF_MLO + cofs) = ml;
                }
        }
        __syncthreads();

        // ---- GEMM2 half: outacc += M_half @ Bc_half ----
        gemm_phase(MHI, MLO, g_W2h, g_W2l, 256, nh * 128,
                   WBUF, outacc, tid, lane, mw, nw);
    }

    // ---- epilogue: out = outacc + bo ----
#pragma unroll
    for (int mb = 0; mb < 2; ++mb)
#pragma unroll
        for (int nb = 0; nb < 4; ++nb) {
            int row = pb + mw * 32 + mb * 16 + r4;
            int col = nw * 32 + nb * 8 + c2;
            float2 b = *(const float2*)(bo + col);
            float2 v0 = make_float2(outacc[mb][nb][0] + b.x, outacc[mb][nb][1] + b.y);
            float2 v1 = make_float2(outacc[mb][nb][2] + b.x, outacc[mb][nb][3] + b.y);
            *(float2*)(&out[(size_t)row * 128 + col]) = v0;
            *(float2*)(&out[(size_t)(row + 8) * 128 + col]) = v1;
        }
}

// ---------------- launch ----------------
extern "C" void kernel_launch(void* const* d_in, const int* in_sizes, int n_in,
                              void* d_out, int out_size) {
    const float* t    = (const float*)d_in[0];
    const float* z    = (const float*)d_in[1];
    const float* mask = (const float*)d_in[2];
    const float* wq   = (const float*)d_in[3];
    const float* wk   = (const float*)d_in[4];
    const float* wv   = (const float*)d_in[5];
    const float* wo   = (const float*)d_in[6];
    const float* bo   = (const float*)d_in[7];
    float* out = (float*)d_out;

    cudaFuncSetAttribute(fused_kernel,
                         cudaFuncAttributeMaxDynamicSharedMemorySize, FSMEM);

    // 1. weights precombine + bf16 hi/lo split
    prep_kernel<<<256, 256>>>(wq, wk, wv, wo);

    // 2. fully fused: z -> U -> attention -> M -> out, per 128-pixel tile
    fused_kernel<<<NPIX / 128, 512, FSMEM>>>(t, z, mask, bo, out);
}

// round 8
// speedup vs baseline: 1.0479x; 1.0479x over previous
#include <cuda_runtime.h>
#include <cuda_bf16.h>
#include <cstdint>

#define NPIX (512*512)
#define CZ 128
#define CT 64
#define NTPL 4
#define NH 4
#define DH 32

// ---------------- device scratch ----------------
__device__ __align__(256) __nv_bfloat16 g_Mh[(size_t)NPIX * 256];  // 128 MB
__device__ __align__(256) __nv_bfloat16 g_Ml[(size_t)NPIX * 256];  // 128 MB
// combined weights, bf16 hi/lo, [n][k] row-major
__device__ __align__(256) __nv_bfloat16 g_W1h[2 * 128 * 128];      // [nh][n][kz]
__device__ __align__(256) __nv_bfloat16 g_W1l[2 * 128 * 128];
__device__ __align__(256) __nv_bfloat16 g_W2h[128 * 256];          // [n][kk]
__device__ __align__(256) __nv_bfloat16 g_W2l[128 * 256];

// ---------------- helpers ----------------
__device__ __forceinline__ uint32_t smem_u32(const void* p) {
    uint32_t a;
    asm("{ .reg .u64 t; cvta.to.shared.u64 t, %1; cvt.u32.u64 %0, t; }" : "=r"(a) : "l"(p));
    return a;
}
__device__ __forceinline__ void ldx4(uint32_t r[4], uint32_t addr) {
    asm volatile("ldmatrix.sync.aligned.m8n8.x4.shared.b16 {%0,%1,%2,%3}, [%4];"
                 : "=r"(r[0]), "=r"(r[1]), "=r"(r[2]), "=r"(r[3]) : "r"(addr));
}
__device__ __forceinline__ void mma16816(float c[4], const uint32_t a[4],
                                         uint32_t b0, uint32_t b1) {
    asm volatile(
        "mma.sync.aligned.m16n8k16.row.col.f32.bf16.bf16.f32 "
        "{%0,%1,%2,%3}, {%4,%5,%6,%7}, {%8,%9}, {%0,%1,%2,%3};"
        : "+f"(c[0]), "+f"(c[1]), "+f"(c[2]), "+f"(c[3])
        : "r"(a[0]), "r"(a[1]), "r"(a[2]), "r"(a[3]), "r"(b0), "r"(b1));
}
__device__ __forceinline__ uint32_t pack_bf2(float x, float y) {
    __nv_bfloat162 p = __halves2bfloat162(__float2bfloat16(x), __float2bfloat16(y));
    return *(uint32_t*)&p;
}
__device__ __forceinline__ void cp16(uint32_t dst, const void* src) {
    asm volatile("cp.async.cg.shared.global [%0], [%1], 16;" :: "r"(dst), "l"(src));
}
__device__ __forceinline__ void cp_commit() { asm volatile("cp.async.commit_group;"); }
__device__ __forceinline__ void cp_wait0() {
    asm volatile("cp.async.wait_group 0;" ::: "memory");
}

// ---------------- prep: combined weights, bf16 hi/lo split ----------------
__global__ void prep_kernel(const float* __restrict__ wq, const float* __restrict__ wk,
                            const float* __restrict__ wv, const float* __restrict__ wo) {
    int id = blockIdx.x * blockDim.x + threadIdx.x;
    float val;
    __nv_bfloat16 *dh, *dl;
    int idx;
    if (id < 32768) {
        int kz = id & 127, n = (id >> 7) & 127, nh = id >> 14;
        int hc = nh * 128 + n;
        int h = hc >> 6, c = hc & 63;
        float s = 0.f;
#pragma unroll
        for (int dd = 0; dd < DH; ++dd)
            s += wq[kz * CZ + h * DH + dd] * wk[c * CZ + h * DH + dd];
        val = s * 0.17677669529663687f;
        dh = g_W1h; dl = g_W1l; idx = id;
    } else {
        int e = id - 32768;
        int kk = e & 255, n = e >> 8;
        int h = kk >> 6, c = kk & 63;
        float s = 0.f;
#pragma unroll
        for (int dd = 0; dd < DH; ++dd)
            s += wv[c * CZ + h * DH + dd] * wo[(h * DH + dd) * CZ + n];
        val = s;
        dh = g_W2h; dl = g_W2l; idx = e;
    }
    __nv_bfloat16 hi = __float2bfloat16(val);
    __nv_bfloat16 lo = __float2bfloat16(val - __bfloat162float(hi));
    dh[idx] = hi;
    dl[idx] = lo;
}

// ===================== Kernel A: z -> U -> attention -> M (bf16 hi/lo) ===============
// 64-pixel tile, 256 threads (8 warps: mw 0..1, nw 0..3), 2 CTAs/SM.
// smem: Zhi @0 (64x272=17408), Zlo @17408, U fp32 @34816 (64x512=32768),
//       Wbuf @67584 (4x10240). total 108544.
static constexpr int A_ZLO = 17408;
static constexpr int A_U = 34816;
static constexpr int A_W = 67584;
static constexpr int ASMEM = 108544;

__global__ __launch_bounds__(256, 2) void fused1_kernel(
    const float* __restrict__ t, const float* __restrict__ z,
    const float* __restrict__ mask) {
    extern __shared__ char sm[];
    const uint32_t sb = smem_u32(sm);
    const int tid = threadIdx.x;
    const int lane = tid & 31;
    const int wid = tid >> 5;
    const int mw = wid & 1, nw = wid >> 1;
    const int pb = blockIdx.x * 64;
    const uint32_t WBUF = sb + A_W;
    float* const Usm = (float*)(sm + A_U);

    // ---- load z tile [64 x 128] fp32, split hi/lo into smem (pitch 272B) ----
#pragma unroll
    for (int i = 0; i < 8; ++i) {
        int idx = tid + 256 * i;              // 0..2047
        int r = idx >> 5, q = idx & 31;
        float4 v = __ldg((const float4*)(z + (size_t)(pb + r) * 128 + q * 4));
        __nv_bfloat16 h0 = __float2bfloat16(v.x), h1 = __float2bfloat16(v.y);
        __nv_bfloat16 h2 = __float2bfloat16(v.z), h3 = __float2bfloat16(v.w);
        uint2 ph, pl;
        ph.x = pack_bf2(v.x, v.y); ph.y = pack_bf2(v.z, v.w);
        pl.x = pack_bf2(v.x - __bfloat162float(h0), v.y - __bfloat162float(h1));
        pl.y = pack_bf2(v.z - __bfloat162float(h2), v.w - __bfloat162float(h3));
        *(uint2*)(sm + r * 272 + q * 8) = ph;
        *(uint2*)(sm + A_ZLO + r * 272 + q * 8) = pl;
    }
    float mbias[NTPL];
#pragma unroll
    for (int nt = 0; nt < NTPL; ++nt)
        mbias[nt] = 100000.0f * (__ldg(mask + nt) - 1.0f);
    __syncthreads();

    const int lrow = lane & 15;
    const int lkb = (lane >> 4) * 16;
    const int r4 = lane >> 2, c2 = (lane & 3) * 2;

#pragma unroll 1
    for (int nh = 0; nh < 2; ++nh) {
        const __nv_bfloat16* __restrict__ Wh = g_W1h + nh * 16384;
        const __nv_bfloat16* __restrict__ Wl = g_W1l + nh * 16384;

        float acc[2][4][4];
#pragma unroll
        for (int i = 0; i < 2; ++i)
#pragma unroll
            for (int j = 0; j < 4; ++j)
#pragma unroll
                for (int q = 0; q < 4; ++q) acc[i][j][q] = 0.f;

        // ---- GEMM1 half: U = Z @ W1[nh], K=128 in 4 chunks, W double-buffered ----
        auto issue = [&](int kt, int s) {
#pragma unroll
            for (int i = 0; i < 4; ++i) {
                int id = tid + 256 * i;        // 0..1023
                int plane = id >> 9;
                int r = (id >> 2) & 127;
                int c = id & 3;
                const __nv_bfloat16* src =
                    (plane ? Wl : Wh) + (size_t)r * 128 + kt * 32 + c * 8;
                cp16(WBUF + (uint32_t)((s * 2 + plane) * 10240 + r * 80 + c * 16), src);
            }
            cp_commit();
        };
        issue(0, 0);
#pragma unroll 1
        for (int kt = 0; kt < 4; ++kt) {
            const int s = kt & 1;
            cp_wait0();
            __syncthreads();
            if (kt < 3) issue(kt + 1, s ^ 1);
            const uint32_t wH = WBUF + (uint32_t)(s * 2) * 10240;
            const uint32_t wL = wH + 10240;
#pragma unroll
            for (int k16 = 0; k16 < 2; ++k16) {
                const uint32_t kbA = (uint32_t)(kt * 64 + k16 * 32 + lkb);
                const uint32_t kbW = (uint32_t)(k16 * 32 + lkb);
                uint32_t bh[2][4], bl[2][4];
#pragma unroll
                for (int ng = 0; ng < 2; ++ng) {
                    uint32_t off = (uint32_t)(nw * 32 + ng * 16 + lrow) * 80 + kbW;
                    ldx4(bh[ng], wH + off);
                    ldx4(bl[ng], wL + off);
                }
#pragma unroll
                for (int mb = 0; mb < 2; ++mb) {
                    uint32_t roff = (uint32_t)(mw * 32 + mb * 16 + lrow) * 272 + kbA;
                    uint32_t ah[4], al[4];
                    ldx4(ah, sb + roff);
                    ldx4(al, sb + A_ZLO + roff);
#pragma unroll
                    for (int nb = 0; nb < 4; ++nb) {
                        const int ng = nb >> 1, hf = nb & 1;
                        mma16816(acc[mb][nb], ah, bh[ng][hf], bh[ng][2 + hf]);
                        mma16816(acc[mb][nb], ah, bl[ng][hf], bl[ng][2 + hf]);
                        mma16816(acc[mb][nb], al, bh[ng][hf], bh[ng][2 + hf]);
                    }
                }
            }
            __syncthreads();
        }

        // ---- write U half to smem (fp32, pitch 128 floats) ----
#pragma unroll
        for (int mb = 0; mb < 2; ++mb)
#pragma unroll
            for (int nb = 0; nb < 4; ++nb) {
                int row = mw * 32 + mb * 16 + r4;
                int col = nw * 32 + nb * 8 + c2;
                *(float2*)(Usm + row * 128 + col) =
                    make_float2(acc[mb][nb][0], acc[mb][nb][1]);
                *(float2*)(Usm + (row + 8) * 128 + col) =
                    make_float2(acc[mb][nb][2], acc[mb][nb][3]);
            }
        __syncthreads();

        // ---- attention: 8 pixels per warp; M straight to gmem (bf16 hi/lo) ----
        float uh[8][2][2];
#pragma unroll
        for (int i = 0; i < 8; ++i) {
            int p = wid * 8 + i;
#pragma unroll
            for (int h2 = 0; h2 < 2; ++h2)
#pragma unroll
                for (int j = 0; j < 2; ++j)
                    uh[i][h2][j] = Usm[p * 128 + h2 * 64 + j * 32 + lane];
        }

#pragma unroll 1
        for (int i = 0; i < 8; ++i) {
            int p = wid * 8 + i;
            float tt[NTPL][2];
#pragma unroll
            for (int nt = 0; nt < NTPL; ++nt)
#pragma unroll
                for (int j = 0; j < 2; ++j)
                    tt[nt][j] = __ldg(t + ((size_t)nt * NPIX + pb + p) * CT + j * 32 + lane);

            float lg[2][NTPL];
#pragma unroll
            for (int h2 = 0; h2 < 2; ++h2)
#pragma unroll
                for (int nt = 0; nt < NTPL; ++nt)
                    lg[h2][nt] = uh[i][h2][0] * tt[nt][0] + uh[i][h2][1] * tt[nt][1];
#pragma unroll
            for (int off = 16; off > 0; off >>= 1)
#pragma unroll
                for (int h2 = 0; h2 < 2; ++h2)
#pragma unroll
                    for (int nt = 0; nt < NTPL; ++nt)
                        lg[h2][nt] += __shfl_xor_sync(0xFFFFFFFFu, lg[h2][nt], off);

            float at[2][NTPL];
#pragma unroll
            for (int h2 = 0; h2 < 2; ++h2) {
                float l0 = lg[h2][0] + mbias[0], l1 = lg[h2][1] + mbias[1];
                float l2 = lg[h2][2] + mbias[2], l3 = lg[h2][3] + mbias[3];
                float mx = fmaxf(fmaxf(l0, l1), fmaxf(l2, l3));
                float e0 = __expf(l0 - mx), e1 = __expf(l1 - mx);
                float e2 = __expf(l2 - mx), e3 = __expf(l3 - mx);
                float inv = __fdividef(1.0f, e0 + e1 + e2 + e3);
                at[h2][0] = e0 * inv; at[h2][1] = e1 * inv;
                at[h2][2] = e2 * inv; at[h2][3] = e3 * inv;
            }
#pragma unroll
            for (int h2 = 0; h2 < 2; ++h2)
#pragma unroll
                for (int j = 0; j < 2; ++j) {
                    float m = at[h2][0] * tt[0][j] + at[h2][1] * tt[1][j] +
                              at[h2][2] * tt[2][j] + at[h2][3] * tt[3][j];
                    __nv_bfloat16 mh = __float2bfloat16(m);
                    __nv_bfloat16 ml = __float2bfloat16(m - __bfloat162float(mh));
                    size_t gidx = (size_t)(pb + p) * 256 + nh * 128 + h2 * 64 + j * 32 + lane;
                    g_Mh[gidx] = mh;
                    g_Ml[gidx] = ml;
                }
        }
        __syncthreads();
    }
}

// ===================== Kernel B: out = M @ Bc + bo (R5 proven GEMM) ==================
// CTA 128x128, 256 threads, warps 2(M)x4(N), warp tile 64x32, BK=32, K=256.
static constexpr int GSMEM = 81920;

__global__ __launch_bounds__(256, 2) void gemm2_kernel(const float* __restrict__ bias,
                                                       float* __restrict__ Cout) {
    extern __shared__ char sm[];
    const uint32_t sbase = smem_u32(sm);
    const int tid = threadIdx.x;
    const int lane = tid & 31;
    const int wid = tid >> 5;
    const int mw = wid & 1, nw = wid >> 1;
    const int pb = blockIdx.x * 128;
    constexpr int KTOT = 256, NC = 8;

    auto issue = [&](int kt, int s) {
#pragma unroll
        for (int i = 0; i < 4; ++i) {
            int id = tid + 256 * i;
            int plane = id >> 9;
            int r = (id >> 2) & 127;
            int c = id & 3;
            const __nv_bfloat16* asrc = (plane ? g_Ml : g_Mh)
                + (size_t)(pb + r) * KTOT + kt * 32 + c * 8;
            cp16(sbase + (uint32_t)((s * 2 + plane) * 10240 + r * 80 + c * 16), asrc);
            const __nv_bfloat16* wsrc = (plane ? g_W2l : g_W2h)
                + (size_t)r * KTOT + kt * 32 + c * 8;
            cp16(sbase + (uint32_t)(40960 + (s * 2 + plane) * 10240 + r * 80 + c * 16), wsrc);
        }
        cp_commit();
    };

    float acc[4][4][4];
#pragma unroll
    for (int i = 0; i < 4; ++i)
#pragma unroll
        for (int j = 0; j < 4; ++j)
#pragma unroll
            for (int q = 0; q < 4; ++q) acc[i][j][q] = 0.f;

    const int lrow = lane & 15;
    const int lkb = (lane >> 4) * 16;

    issue(0, 0);

    for (int kt = 0; kt < NC; ++kt) {
        const int s = kt & 1;
        cp_wait0();
        __syncthreads();
        if (kt + 1 < NC) issue(kt + 1, s ^ 1);

        const uint32_t aBh = sbase + (uint32_t)(s * 2) * 10240;
        const uint32_t aBl = aBh + 10240;
        const uint32_t wBh = sbase + 40960u + (uint32_t)(s * 2) * 10240;
        const uint32_t wBl = wBh + 10240;

#pragma unroll
        for (int k16 = 0; k16 < 2; ++k16) {
            const uint32_t kbyte = k16 * 32 + lkb;
            uint32_t bh[2][4], bl[2][4];
#pragma unroll
            for (int ng = 0; ng < 2; ++ng) {
                uint32_t off = (uint32_t)(nw * 32 + ng * 16 + lrow) * 80 + kbyte;
                ldx4(bh[ng], wBh + off);
                ldx4(bl[ng], wBl + off);
            }
#pragma unroll
            for (int mb = 0; mb < 4; ++mb) {
                uint32_t off = (uint32_t)(mw * 64 + mb * 16 + lrow) * 80 + kbyte;
                uint32_t ah[4], al[4];
                ldx4(ah, aBh + off);
                ldx4(al, aBl + off);
#pragma unroll
                for (int nb = 0; nb < 4; ++nb) {
                    const int ng = nb >> 1, hf = nb & 1;
                    mma16816(acc[mb][nb], ah, bh[ng][hf], bh[ng][2 + hf]);
                    mma16816(acc[mb][nb], ah, bl[ng][hf], bl[ng][2 + hf]);
                    mma16816(acc[mb][nb], al, bh[ng][hf], bh[ng][2 + hf]);
                }
            }
        }
        __syncthreads();
    }

    const int r4 = lane >> 2, c2 = (lane & 3) * 2;
#pragma unroll
    for (int mb = 0; mb < 4; ++mb)
#pragma unroll
        for (int nb = 0; nb < 4; ++nb) {
            int row = pb + mw * 64 + mb * 16 + r4;
            int col = nw * 32 + nb * 8 + c2;
            float2 b = *(const float2*)(bias + col);
            float2 v0 = make_float2(acc[mb][nb][0] + b.x, acc[mb][nb][1] + b.y);
            float2 v1 = make_float2(acc[mb][nb][2] + b.x, acc[mb][nb][3] + b.y);
            *(float2*)(&Cout[(size_t)row * 128 + col]) = v0;
            *(float2*)(&Cout[(size_t)(row + 8) * 128 + col]) = v1;
        }
}

// ---------------- launch ----------------
extern "C" void kernel_launch(void* const* d_in, const int* in_sizes, int n_in,
                              void* d_out, int out_size) {
    const float* t    = (const float*)d_in[0];
    const float* z    = (const float*)d_in[1];
    const float* mask = (const float*)d_in[2];
    const float* wq   = (const float*)d_in[3];
    const float* wk   = (const float*)d_in[4];
    const float* wv   = (const float*)d_in[5];
    const float* wo   = (const float*)d_in[6];
    const float* bo   = (const float*)d_in[7];
    float* out = (float*)d_out;

    cudaFuncSetAttribute(fused1_kernel,
                         cudaFuncAttributeMaxDynamicSharedMemorySize, ASMEM);
    cudaFuncSetAttribute(gemm2_kernel,
                         cudaFuncAttributeMaxDynamicSharedMemorySize, GSMEM);

    // 1. weights precombine + bf16 hi/lo split
    prep_kernel<<<256, 256>>>(wq, wk, wv, wo);

    // 2. fused GEMM1 + attention: z, t, mask -> M (bf16 hi/lo planes)
    fused1_kernel<<<NPIX / 64, 256, ASMEM>>>(t, z, mask);

    // 3. out = M @ Bc + bo
    gemm2_kernel<<<NPIX / 128, 256, GSMEM>>>(bo, out);
}

// round 9
// speedup vs baseline: 1.0865x; 1.0368x over previous
#include <cuda_runtime.h>
#include <cuda_bf16.h>
#include <cstdint>

#define NPIX (512*512)
#define CZ 128
#define CT 64
#define NTPL 4
#define NH 4
#define DH 32

// ---------------- device scratch ----------------
__device__ __align__(256) __nv_bfloat16 g_zh[(size_t)NPIX * 128];
__device__ __align__(256) __nv_bfloat16 g_zl[(size_t)NPIX * 128];
__device__ __align__(256) __nv_bfloat16 g_Uh[(size_t)NPIX * 256];
__device__ __align__(256) __nv_bfloat16 g_Ul[(size_t)NPIX * 256];
__device__ __align__(256) __nv_bfloat16 g_Mh[(size_t)NPIX * 256];
__device__ __align__(256) __nv_bfloat16 g_Ml[(size_t)NPIX * 256];
// combined weights, bf16 hi/lo, [n][k] row-major
__device__ __align__(256) __nv_bfloat16 g_W1h[2 * 128 * 128];  // [nh][n][kz]
__device__ __align__(256) __nv_bfloat16 g_W1l[2 * 128 * 128];
__device__ __align__(256) __nv_bfloat16 g_W2h[128 * 256];      // [n][kk]
__device__ __align__(256) __nv_bfloat16 g_W2l[128 * 256];

// ---------------- helpers ----------------
__device__ __forceinline__ uint32_t smem_u32(const void* p) {
    uint32_t a;
    asm("{ .reg .u64 t; cvta.to.shared.u64 t, %1; cvt.u32.u64 %0, t; }" : "=r"(a) : "l"(p));
    return a;
}
__device__ __forceinline__ void ldx4(uint32_t r[4], uint32_t addr) {
    asm volatile("ldmatrix.sync.aligned.m8n8.x4.shared.b16 {%0,%1,%2,%3}, [%4];"
                 : "=r"(r[0]), "=r"(r[1]), "=r"(r[2]), "=r"(r[3]) : "r"(addr));
}
__device__ __forceinline__ void mma16816(float c[4], const uint32_t a[4],
                                         uint32_t b0, uint32_t b1) {
    asm volatile(
        "mma.sync.aligned.m16n8k16.row.col.f32.bf16.bf16.f32 "
        "{%0,%1,%2,%3}, {%4,%5,%6,%7}, {%8,%9}, {%0,%1,%2,%3};"
        : "+f"(c[0]), "+f"(c[1]), "+f"(c[2]), "+f"(c[3])
        : "r"(a[0]), "r"(a[1]), "r"(a[2]), "r"(a[3]), "r"(b0), "r"(b1));
}
__device__ __forceinline__ uint32_t pack_bf2(float x, float y) {
    __nv_bfloat162 p = __halves2bfloat162(__float2bfloat16(x), __float2bfloat16(y));
    return *(uint32_t*)&p;
}
__device__ __forceinline__ void cp16(uint32_t dst, const void* src) {
    asm volatile("cp.async.cg.shared.global [%0], [%1], 16;" :: "r"(dst), "l"(src));
}
__device__ __forceinline__ void cp_commit() { asm volatile("cp.async.commit_group;"); }
__device__ __forceinline__ void cp_wait0() {
    asm volatile("cp.async.wait_group 0;" ::: "memory");
}

// ---------------- prep: combined weights, bf16 hi/lo split ----------------
__global__ void prep_kernel(const float* __restrict__ wq, const float* __restrict__ wk,
                            const float* __restrict__ wv, const float* __restrict__ wo) {
    int id = blockIdx.x * blockDim.x + threadIdx.x;
    float val;
    __nv_bfloat16 *dh, *dl;
    int idx;
    if (id < 32768) {
        int kz = id & 127, n = (id >> 7) & 127, nh = id >> 14;
        int hc = nh * 128 + n;
        int h = hc >> 6, c = hc & 63;
        float s = 0.f;
#pragma unroll
        for (int dd = 0; dd < DH; ++dd)
            s += wq[kz * CZ + h * DH + dd] * wk[c * CZ + h * DH + dd];
        val = s * 0.17677669529663687f;
        dh = g_W1h; dl = g_W1l; idx = id;
    } else {
        int e = id - 32768;
        int kk = e & 255, n = e >> 8;
        int h = kk >> 6, c = kk & 63;
        float s = 0.f;
#pragma unroll
        for (int dd = 0; dd < DH; ++dd)
            s += wv[c * CZ + h * DH + dd] * wo[(h * DH + dd) * CZ + n];
        val = s;
        dh = g_W2h; dl = g_W2l; idx = e;
    }
    __nv_bfloat16 hi = __float2bfloat16(val);
    __nv_bfloat16 lo = __float2bfloat16(val - __bfloat162float(hi));
    dh[idx] = hi;
    dl[idx] = lo;
}

// ---------------- convz: z fp32 -> planar bf16 hi/lo ----------------
__global__ void convz_kernel(const float* __restrict__ z) {
    size_t i = ((size_t)blockIdx.x * 256 + threadIdx.x) * 4;
    float4 v = *(const float4*)(z + i);
    __nv_bfloat16 h0 = __float2bfloat16(v.x), h1 = __float2bfloat16(v.y);
    __nv_bfloat16 h2 = __float2bfloat16(v.z), h3 = __float2bfloat16(v.w);
    uint2 ph, pl;
    ph.x = pack_bf2(v.x, v.y); ph.y = pack_bf2(v.z, v.w);
    pl.x = pack_bf2(v.x - __bfloat162float(h0), v.y - __bfloat162float(h1));
    pl.y = pack_bf2(v.z - __bfloat162float(h2), v.w - __bfloat162float(h3));
    *(uint2*)(g_zh + i) = ph;
    *(uint2*)(g_zl + i) = pl;
}

// ---------------- cp.async double-buffered bf16-split GEMM ----------------
// CTA 128x128, 256 threads, warps 2(M)x4(N), warp tile 64x32, BK=32.
// MODE 0: A = zh/zl (K=128), out = Uh/Ul bf16 planes (stride 256, colbase nh*128)
// MODE 1: A = Mh/Ml (K=256), out = fp32 Cout (+bias, stride 128)
static constexpr int GSMEM = 81920;

template <int KTOT, int MODE, bool BIAS>
__global__ __launch_bounds__(256, 2) void tgemm(const float* __restrict__ bias,
                                                float* __restrict__ Cout) {
    extern __shared__ char sm[];
    const uint32_t sbase = smem_u32(sm);
    const int tid = threadIdx.x;
    const int lane = tid & 31;
    const int wid = tid >> 5;
    const int mw = wid & 1, nw = wid >> 1;
    const int pb = blockIdx.x * 128;
    const int nh = (MODE == 0) ? blockIdx.y : 0;
    constexpr int NC = KTOT / 32;

    const __nv_bfloat16* __restrict__ Ah = (MODE == 0) ? g_zh : g_Mh;
    const __nv_bfloat16* __restrict__ Al = (MODE == 0) ? g_zl : g_Ml;
    const __nv_bfloat16* __restrict__ Wh = (MODE == 0) ? g_W1h + nh * 16384 : g_W2h;
    const __nv_bfloat16* __restrict__ Wl = (MODE == 0) ? g_W1l + nh * 16384 : g_W2l;
    const int colbase = (MODE == 0) ? nh * 128 : 0;

    auto issue = [&](int kt, int s) {
#pragma unroll
        for (int i = 0; i < 4; ++i) {
            int id = tid + 256 * i;
            int plane = id >> 9;
            int r = (id >> 2) & 127;
            int c = id & 3;
            const __nv_bfloat16* asrc = (plane ? Al : Ah)
                + (size_t)(pb + r) * KTOT + kt * 32 + c * 8;
            cp16(sbase + (uint32_t)((s * 2 + plane) * 10240 + r * 80 + c * 16), asrc);
            const __nv_bfloat16* wsrc = (plane ? Wl : Wh)
                + (size_t)r * KTOT + kt * 32 + c * 8;
            cp16(sbase + (uint32_t)(40960 + (s * 2 + plane) * 10240 + r * 80 + c * 16), wsrc);
        }
        cp_commit();
    };

    float acc[4][4][4];
#pragma unroll
    for (int i = 0; i < 4; ++i)
#pragma unroll
        for (int j = 0; j < 4; ++j)
#pragma unroll
            for (int q = 0; q < 4; ++q) acc[i][j][q] = 0.f;

    const int lrow = lane & 15;
    const int lkb = (lane >> 4) * 16;

    issue(0, 0);

    for (int kt = 0; kt < NC; ++kt) {
        const int s = kt & 1;
        cp_wait0();
        __syncthreads();
        if (kt + 1 < NC) issue(kt + 1, s ^ 1);

        const uint32_t aBh = sbase + (uint32_t)(s * 2) * 10240;
        const uint32_t aBl = aBh + 10240;
        const uint32_t wBh = sbase + 40960u + (uint32_t)(s * 2) * 10240;
        const uint32_t wBl = wBh + 10240;

#pragma unroll
        for (int k16 = 0; k16 < 2; ++k16) {
            const uint32_t kbyte = k16 * 32 + lkb;
            uint32_t bh[2][4], bl[2][4];
#pragma unroll
            for (int ng = 0; ng < 2; ++ng) {
                uint32_t off = (uint32_t)(nw * 32 + ng * 16 + lrow) * 80 + kbyte;
                ldx4(bh[ng], wBh + off);
                ldx4(bl[ng], wBl + off);
            }
#pragma unroll
            for (int mb = 0; mb < 4; ++mb) {
                uint32_t off = (uint32_t)(mw * 64 + mb * 16 + lrow) * 80 + kbyte;
                uint32_t ah[4], al[4];
                ldx4(ah, aBh + off);
                ldx4(al, aBl + off);
#pragma unroll
                for (int nb = 0; nb < 4; ++nb) {
                    const int ng = nb >> 1, hf = nb & 1;
                    mma16816(acc[mb][nb], ah, bh[ng][hf], bh[ng][2 + hf]);
                    mma16816(acc[mb][nb], ah, bl[ng][hf], bl[ng][2 + hf]);
                    mma16816(acc[mb][nb], al, bh[ng][hf], bh[ng][2 + hf]);
                }
            }
        }
        // trailing sync removed: next iteration's wait+sync orders compute-done
        // before its slot is reissued.
    }

    const int r4 = lane >> 2, c2 = (lane & 3) * 2;
#pragma unroll
    for (int mb = 0; mb < 4; ++mb)
#pragma unroll
        for (int nb = 0; nb < 4; ++nb) {
            int row = pb + mw * 64 + mb * 16 + r4;
            int col = colbase + nw * 32 + nb * 8 + c2;
            if (MODE == 0) {
                // write U as bf16 hi/lo pairs
#pragma unroll
                for (int rr = 0; rr < 2; ++rr) {
                    float x = acc[mb][nb][rr * 2 + 0];
                    float y = acc[mb][nb][rr * 2 + 1];
                    __nv_bfloat16 hx = __float2bfloat16(x), hy = __float2bfloat16(y);
                    size_t o = (size_t)(row + rr * 8) * 256 + col;
                    *(uint32_t*)(g_Uh + o) = pack_bf2(x, y);
                    *(uint32_t*)(g_Ul + o) =
                        pack_bf2(x - __bfloat162float(hx), y - __bfloat162float(hy));
                }
            } else {
                float2 b = *(const float2*)(bias + col);
                float2 v0 = make_float2(acc[mb][nb][0] + b.x, acc[mb][nb][1] + b.y);
                float2 v1 = make_float2(acc[mb][nb][2] + b.x, acc[mb][nb][3] + b.y);
                *(float2*)(&Cout[(size_t)row * 128 + col]) = v0;
                *(float2*)(&Cout[(size_t)(row + 8) * 128 + col]) = v1;
            }
        }
}

// ---------------- per-pixel attention (warp per pixel), vectorized ----------------
// lane owns cols {2l, 2l+1}; U bf16 hi/lo, t float2, M bf16x2 stores.
__global__ void attn_kernel(const float* __restrict__ t, const float* __restrict__ mask) {
    int p = blockIdx.x * 8 + (threadIdx.x >> 5);
    int l = threadIdx.x & 31;

    float2 u[NH];
#pragma unroll
    for (int h = 0; h < NH; ++h) {
        size_t o = (size_t)p * 256 + h * 64 + 2 * l;
        uint32_t rh = *(const uint32_t*)(g_Uh + o);
        uint32_t rl = *(const uint32_t*)(g_Ul + o);
        __nv_bfloat162 bh = *(__nv_bfloat162*)&rh;
        __nv_bfloat162 bl = *(__nv_bfloat162*)&rl;
        u[h].x = __bfloat162float(__low2bfloat16(bh)) + __bfloat162float(__low2bfloat16(bl));
        u[h].y = __bfloat162float(__high2bfloat16(bh)) + __bfloat162float(__high2bfloat16(bl));
    }

    float2 tt[NTPL];
#pragma unroll
    for (int nt = 0; nt < NTPL; ++nt)
        tt[nt] = *(const float2*)(t + ((size_t)nt * NPIX + p) * CT + 2 * l);

    float lg[NH][NTPL];
#pragma unroll
    for (int h = 0; h < NH; ++h)
#pragma unroll
        for (int nt = 0; nt < NTPL; ++nt)
            lg[h][nt] = u[h].x * tt[nt].x + u[h].y * tt[nt].y;

#pragma unroll
    for (int off = 16; off > 0; off >>= 1)
#pragma unroll
        for (int h = 0; h < NH; ++h)
#pragma unroll
            for (int nt = 0; nt < NTPL; ++nt)
                lg[h][nt] += __shfl_xor_sync(0xFFFFFFFFu, lg[h][nt], off);

    float bias[NTPL];
#pragma unroll
    for (int nt = 0; nt < NTPL; ++nt) bias[nt] = 100000.0f * (__ldg(mask + nt) - 1.0f);

    float at[NH][NTPL];
#pragma unroll
    for (int h = 0; h < NH; ++h) {
        float l0 = lg[h][0] + bias[0], l1 = lg[h][1] + bias[1];
        float l2 = lg[h][2] + bias[2], l3 = lg[h][3] + bias[3];
        float mx = fmaxf(fmaxf(l0, l1), fmaxf(l2, l3));
        float e0 = __expf(l0 - mx), e1 = __expf(l1 - mx);
        float e2 = __expf(l2 - mx), e3 = __expf(l3 - mx);
        float inv = __fdividef(1.0f, e0 + e1 + e2 + e3);
        at[h][0] = e0 * inv; at[h][1] = e1 * inv;
        at[h][2] = e2 * inv; at[h][3] = e3 * inv;
    }

#pragma unroll
    for (int h = 0; h < NH; ++h) {
        float mx = at[h][0] * tt[0].x + at[h][1] * tt[1].x +
                   at[h][2] * tt[2].x + at[h][3] * tt[3].x;
        float my = at[h][0] * tt[0].y + at[h][1] * tt[1].y +
                   at[h][2] * tt[2].y + at[h][3] * tt[3].y;
        __nv_bfloat16 hx = __float2bfloat16(mx), hy = __float2bfloat16(my);
        size_t o = (size_t)p * 256 + h * 64 + 2 * l;
        *(uint32_t*)(g_Mh + o) = pack_bf2(mx, my);
        *(uint32_t*)(g_Ml + o) =
            pack_bf2(mx - __bfloat162float(hx), my - __bfloat162float(hy));
    }
}

// ---------------- launch ----------------
extern "C" void kernel_launch(void* const* d_in, const int* in_sizes, int n_in,
                              void* d_out, int out_size) {
    const float* t    = (const float*)d_in[0];
    const float* z    = (const float*)d_in[1];
    const float* mask = (const float*)d_in[2];
    const float* wq   = (const float*)d_in[3];
    const float* wk   = (const float*)d_in[4];
    const float* wv   = (const float*)d_in[5];
    const float* wo   = (const float*)d_in[6];
    const float* bo   = (const float*)d_in[7];
    float* out = (float*)d_out;

    cudaFuncSetAttribute(tgemm<128, 0, false>,
                         cudaFuncAttributeMaxDynamicSharedMemorySize, GSMEM);
    cudaFuncSetAttribute(tgemm<256, 1, true>,
                         cudaFuncAttributeMaxDynamicSharedMemorySize, GSMEM);

    // 1. weights precombine + split; z split
    prep_kernel<<<256, 256>>>(wq, wk, wv, wo);
    convz_kernel<<<NPIX * 128 / 1024, 256>>>(z);

    // 2. U = Z @ Ac  (bf16 hi/lo output)
    tgemm<128, 0, false><<<dim3(NPIX / 128, 2), 256, GSMEM>>>(nullptr, nullptr);

    // 3. attention: U, t, mask -> M (bf16 hi/lo)
    attn_kernel<<<NPIX / 8, 256>>>(t, mask);

    // 4. out = M @ Bc + bo
    tgemm<256, 1, true><<<dim3(NPIX / 128, 1), 256, GSMEM>>>(bo, out);
}

// round 10
// speedup vs baseline: 1.2613x; 1.1609x over previous
#include <cuda_runtime.h>
#include <cuda_bf16.h>
#include <cstdint>

#define NPIX (512*512)
#define CZ 128
#define CT 64
#define NTPL 4
#define NH 4
#define DH 32

// ---------------- device scratch ----------------
__device__ __align__(256) float g_U[(size_t)NPIX * 256];           // 256 MB fp32
__device__ __align__(256) __nv_bfloat16 g_Mh[(size_t)NPIX * 256];  // 128 MB
__device__ __align__(256) __nv_bfloat16 g_Ml[(size_t)NPIX * 256];  // 128 MB
// combined weights, bf16 hi/lo, [n][k] row-major
__device__ __align__(256) __nv_bfloat16 g_W1h[2 * 128 * 128];      // [nh][n][kz]
__device__ __align__(256) __nv_bfloat16 g_W1l[2 * 128 * 128];
__device__ __align__(256) __nv_bfloat16 g_W2h[128 * 256];          // [n][kk]
__device__ __align__(256) __nv_bfloat16 g_W2l[128 * 256];

// ---------------- helpers ----------------
__device__ __forceinline__ uint32_t smem_u32(const void* p) {
    uint32_t a;
    asm("{ .reg .u64 t; cvta.to.shared.u64 t, %1; cvt.u32.u64 %0, t; }" : "=r"(a) : "l"(p));
    return a;
}
__device__ __forceinline__ void ldx4(uint32_t r[4], uint32_t addr) {
    asm volatile("ldmatrix.sync.aligned.m8n8.x4.shared.b16 {%0,%1,%2,%3}, [%4];"
                 : "=r"(r[0]), "=r"(r[1]), "=r"(r[2]), "=r"(r[3]) : "r"(addr));
}
__device__ __forceinline__ void mma16816(float c[4], const uint32_t a[4],
                                         uint32_t b0, uint32_t b1) {
    asm volatile(
        "mma.sync.aligned.m16n8k16.row.col.f32.bf16.bf16.f32 "
        "{%0,%1,%2,%3}, {%4,%5,%6,%7}, {%8,%9}, {%0,%1,%2,%3};"
        : "+f"(c[0]), "+f"(c[1]), "+f"(c[2]), "+f"(c[3])
        : "r"(a[0]), "r"(a[1]), "r"(a[2]), "r"(a[3]), "r"(b0), "r"(b1));
}
__device__ __forceinline__ uint32_t pack_bf2(float x, float y) {
    __nv_bfloat162 p = __halves2bfloat162(__float2bfloat16(x), __float2bfloat16(y));
    return *(uint32_t*)&p;
}
__device__ __forceinline__ void cp16(uint32_t dst, const void* src) {
    asm volatile("cp.async.cg.shared.global [%0], [%1], 16;" :: "r"(dst), "l"(src));
}
__device__ __forceinline__ void cp_commit() { asm volatile("cp.async.commit_group;"); }
__device__ __forceinline__ void cp_wait0() {
    asm volatile("cp.async.wait_group 0;" ::: "memory");
}

// ---------------- prep: combined weights, bf16 hi/lo split ----------------
__global__ void prep_kernel(const float* __restrict__ wq, const float* __restrict__ wk,
                            const float* __restrict__ wv, const float* __restrict__ wo) {
    int id = blockIdx.x * blockDim.x + threadIdx.x;
    float val;
    __nv_bfloat16 *dh, *dl;
    int idx;
    if (id < 32768) {
        int kz = id & 127, n = (id >> 7) & 127, nh = id >> 14;
        int hc = nh * 128 + n;
        int h = hc >> 6, c = hc & 63;
        float s = 0.f;
#pragma unroll
        for (int dd = 0; dd < DH; ++dd)
            s += wq[kz * CZ + h * DH + dd] * wk[c * CZ + h * DH + dd];
        val = s * 0.17677669529663687f;
        dh = g_W1h; dl = g_W1l; idx = id;
    } else {
        int e = id - 32768;
        int kk = e & 255, n = e >> 8;
        int h = kk >> 6, c = kk & 63;
        float s = 0.f;
#pragma unroll
        for (int dd = 0; dd < DH; ++dd)
            s += wv[c * CZ + h * DH + dd] * wo[(h * DH + dd) * CZ + n];
        val = s;
        dh = g_W2h; dl = g_W2l; idx = e;
    }
    __nv_bfloat16 hi = __float2bfloat16(val);
    __nv_bfloat16 lo = __float2bfloat16(val - __bfloat162float(hi));
    dh[idx] = hi;
    dl[idx] = lo;
}

// ===================== GEMM1: U = Z @ W1, fp32 z in, in-smem split =====================
// CTA 128x128, 256 threads, warps 2(M)x4(N), warp tile 64x32, K=128 (4 chunks of 32).
// smem: Ahi @0 (10240), Alo @10240, W 2stage x 2plane @20480 (40960), zstage @61440 (16384).
static constexpr int G1_AL = 10240;
static constexpr int G1_W = 20480;
static constexpr int G1_STG = 61440;
static constexpr int G1SMEM = 77824;

__global__ __launch_bounds__(256, 2) void gemm1_kernel(const float* __restrict__ z) {
    extern __shared__ char sm[];
    const uint32_t sbase = smem_u32(sm);
    const int tid = threadIdx.x;
    const int lane = tid & 31;
    const int wid = tid >> 5;
    const int mw = wid & 1, nw = wid >> 1;
    const int pb = blockIdx.x * 128;
    const int nh = blockIdx.y;

    const __nv_bfloat16* __restrict__ Wh = g_W1h + nh * 16384;
    const __nv_bfloat16* __restrict__ Wl = g_W1l + nh * 16384;

    auto issue = [&](int kt, int s) {
        // z fp32 chunk [128 x 32] -> staging (pitch 128B)
#pragma unroll
        for (int i = 0; i < 4; ++i) {
            int id = tid + 256 * i;            // 0..1023
            int r = id >> 3, c = id & 7;
            cp16(sbase + (uint32_t)(G1_STG + r * 128 + c * 16),
                 z + (size_t)(pb + r) * 128 + kt * 32 + c * 4);
        }
        // W hi/lo chunk [128 x 32] bf16 -> W[s] (pitch 80B)
#pragma unroll
        for (int i = 0; i < 4; ++i) {
            int id = tid + 256 * i;
            int plane = id >> 9;
            int r = (id >> 2) & 127;
            int c = id & 3;
            cp16(sbase + (uint32_t)(G1_W + (s * 2 + plane) * 10240 + r * 80 + c * 16),
                 (plane ? Wl : Wh) + (size_t)r * 128 + kt * 32 + c * 8);
        }
        cp_commit();
    };

    float acc[4][4][4];
#pragma unroll
    for (int i = 0; i < 4; ++i)
#pragma unroll
        for (int j = 0; j < 4; ++j)
#pragma unroll
            for (int q = 0; q < 4; ++q) acc[i][j][q] = 0.f;

    const int lrow = lane & 15;
    const int lkb = (lane >> 4) * 16;

    issue(0, 0);

    for (int kt = 0; kt < 4; ++kt) {
        const int s = kt & 1;
        cp_wait0();
        __syncthreads();

        // convert staging fp32 -> hi/lo bf16 A planes (thread: row tid>>1, 16 floats)
        {
            int r = tid >> 1, half = tid & 1;
            const float4* src = (const float4*)(sm + G1_STG + r * 128 + half * 64);
            uint32_t hi[4], lo[4];
#pragma unroll
            for (int j = 0; j < 4; ++j) {
                float4 v = src[j];
                __nv_bfloat16 h0 = __float2bfloat16(v.x), h1 = __float2bfloat16(v.y);
                __nv_bfloat16 h2 = __float2bfloat16(v.z), h3 = __float2bfloat16(v.w);
                hi[j] = pack_bf2(v.x, v.y);
                lo[j] = pack_bf2(v.x - __bfloat162float(h0), v.y - __bfloat162float(h1));
                // second pair goes into next slot
                if (j & 1) { }
                // pack z,w into adjacent words via a second pass below
                hi[j] = hi[j]; // placeholder to keep structure simple
                // We'll instead write 2 words per float4:
                uint32_t hiw2 = pack_bf2(v.z, v.w);
                uint32_t low2 = pack_bf2(v.z - __bfloat162float(h2), v.w - __bfloat162float(h3));
                uint32_t base = (uint32_t)(r * 80 + half * 32 + j * 8);
                *(uint32_t*)(sm + base) = hi[j];
                *(uint32_t*)(sm + base + 4) = hiw2;
                *(uint32_t*)(sm + G1_AL + base) = lo[j];
                *(uint32_t*)(sm + G1_AL + base + 4) = low2;
            }
        }
        __syncthreads();

        if (kt < 3) issue(kt + 1, s ^ 1);

        const uint32_t aBh = sbase;
        const uint32_t aBl = sbase + G1_AL;
        const uint32_t wBh = sbase + (uint32_t)(G1_W + s * 2 * 10240);
        const uint32_t wBl = wBh + 10240;

#pragma unroll
        for (int k16 = 0; k16 < 2; ++k16) {
            const uint32_t kbyte = k16 * 32 + lkb;
            uint32_t bh[2][4], bl[2][4];
#pragma unroll
            for (int ng = 0; ng < 2; ++ng) {
                uint32_t off = (uint32_t)(nw * 32 + ng * 16 + lrow) * 80 + kbyte;
                ldx4(bh[ng], wBh + off);
                ldx4(bl[ng], wBl + off);
            }
#pragma unroll
            for (int mb = 0; mb < 4; ++mb) {
                uint32_t off = (uint32_t)(mw * 64 + mb * 16 + lrow) * 80 + kbyte;
                uint32_t ah[4], al[4];
                ldx4(ah, aBh + off);
                ldx4(al, aBl + off);
#pragma unroll
                for (int nb = 0; nb < 4; ++nb) {
                    const int ng = nb >> 1, hf = nb & 1;
                    mma16816(acc[mb][nb], ah, bh[ng][hf], bh[ng][2 + hf]);
                    mma16816(acc[mb][nb], ah, bl[ng][hf], bl[ng][2 + hf]);
                    mma16816(acc[mb][nb], al, bh[ng][hf], bh[ng][2 + hf]);
                }
            }
        }
    }

    // epilogue: fp32 U (stride 256, colbase nh*128)
    const int r4 = lane >> 2, c2 = (lane & 3) * 2;
#pragma unroll
    for (int mb = 0; mb < 4; ++mb)
#pragma unroll
        for (int nb = 0; nb < 4; ++nb) {
            int row = pb + mw * 64 + mb * 16 + r4;
            int col = nh * 128 + nw * 32 + nb * 8 + c2;
            *(float2*)(&g_U[(size_t)row * 256 + col]) =
                make_float2(acc[mb][nb][0], acc[mb][nb][1]);
            *(float2*)(&g_U[(size_t)(row + 8) * 256 + col]) =
                make_float2(acc[mb][nb][2], acc[mb][nb][3]);
        }
}

// ===================== GEMM2: out = M @ Bc + bo =====================
static constexpr int GSMEM = 81920;

__global__ __launch_bounds__(256, 2) void gemm2_kernel(const float* __restrict__ bias,
                                                       float* __restrict__ Cout) {
    extern __shared__ char sm[];
    const uint32_t sbase = smem_u32(sm);
    const int tid = threadIdx.x;
    const int lane = tid & 31;
    const int wid = tid >> 5;
    const int mw = wid & 1, nw = wid >> 1;
    const int pb = blockIdx.x * 128;
    constexpr int KTOT = 256, NC = 8;

    auto issue = [&](int kt, int s) {
#pragma unroll
        for (int i = 0; i < 4; ++i) {
            int id = tid + 256 * i;
            int plane = id >> 9;
            int r = (id >> 2) & 127;
            int c = id & 3;
            const __nv_bfloat16* asrc = (plane ? g_Ml : g_Mh)
                + (size_t)(pb + r) * KTOT + kt * 32 + c * 8;
            cp16(sbase + (uint32_t)((s * 2 + plane) * 10240 + r * 80 + c * 16), asrc);
            const __nv_bfloat16* wsrc = (plane ? g_W2l : g_W2h)
                + (size_t)r * KTOT + kt * 32 + c * 8;
            cp16(sbase + (uint32_t)(40960 + (s * 2 + plane) * 10240 + r * 80 + c * 16), wsrc);
        }
        cp_commit();
    };

    float acc[4][4][4];
#pragma unroll
    for (int i = 0; i < 4; ++i)
#pragma unroll
        for (int j = 0; j < 4; ++j)
#pragma unroll
            for (int q = 0; q < 4; ++q) acc[i][j][q] = 0.f;

    const int lrow = lane & 15;
    const int lkb = (lane >> 4) * 16;

    issue(0, 0);

    for (int kt = 0; kt < NC; ++kt) {
        const int s = kt & 1;
        cp_wait0();
        __syncthreads();
        if (kt + 1 < NC) issue(kt + 1, s ^ 1);

        const uint32_t aBh = sbase + (uint32_t)(s * 2) * 10240;
        const uint32_t aBl = aBh + 10240;
        const uint32_t wBh = sbase + 40960u + (uint32_t)(s * 2) * 10240;
        const uint32_t wBl = wBh + 10240;

#pragma unroll
        for (int k16 = 0; k16 < 2; ++k16) {
            const uint32_t kbyte = k16 * 32 + lkb;
            uint32_t bh[2][4], bl[2][4];
#pragma unroll
            for (int ng = 0; ng < 2; ++ng) {
                uint32_t off = (uint32_t)(nw * 32 + ng * 16 + lrow) * 80 + kbyte;
                ldx4(bh[ng], wBh + off);
                ldx4(bl[ng], wBl + off);
            }
#pragma unroll
            for (int mb = 0; mb < 4; ++mb) {
                uint32_t off = (uint32_t)(mw * 64 + mb * 16 + lrow) * 80 + kbyte;
                uint32_t ah[4], al[4];
                ldx4(ah, aBh + off);
                ldx4(al, aBl + off);
#pragma unroll
                for (int nb = 0; nb < 4; ++nb) {
                    const int ng = nb >> 1, hf = nb & 1;
                    mma16816(acc[mb][nb], ah, bh[ng][hf], bh[ng][2 + hf]);
                    mma16816(acc[mb][nb], ah, bl[ng][hf], bl[ng][2 + hf]);
                    mma16816(acc[mb][nb], al, bh[ng][hf], bh[ng][2 + hf]);
                }
            }
        }
    }

    const int r4 = lane >> 2, c2 = (lane & 3) * 2;
#pragma unroll
    for (int mb = 0; mb < 4; ++mb)
#pragma unroll
        for (int nb = 0; nb < 4; ++nb) {
            int row = pb + mw * 64 + mb * 16 + r4;
            int col = nw * 32 + nb * 8 + c2;
            float2 b = *(const float2*)(bias + col);
            float2 v0 = make_float2(acc[mb][nb][0] + b.x, acc[mb][nb][1] + b.y);
            float2 v1 = make_float2(acc[mb][nb][2] + b.x, acc[mb][nb][3] + b.y);
            *(float2*)(&Cout[(size_t)row * 128 + col]) = v0;
            *(float2*)(&Cout[(size_t)(row + 8) * 128 + col]) = v1;
        }
}

// ---------------- per-pixel attention (warp per pixel), vectorized ----------------
// lane owns cols {2l, 2l+1}; U fp32 float2, t float2, M bf16x2 stores.
__global__ void attn_kernel(const float* __restrict__ t, const float* __restrict__ mask) {
    int p = blockIdx.x * 8 + (threadIdx.x >> 5);
    int l = threadIdx.x & 31;

    float2 u[NH];
#pragma unroll
    for (int h = 0; h < NH; ++h)
        u[h] = *(const float2*)(g_U + (size_t)p * 256 + h * 64 + 2 * l);

    float2 tt[NTPL];
#pragma unroll
    for (int nt = 0; nt < NTPL; ++nt)
        tt[nt] = *(const float2*)(t + ((size_t)nt * NPIX + p) * CT + 2 * l);

    float lg[NH][NTPL];
#pragma unroll
    for (int h = 0; h < NH; ++h)
#pragma unroll
        for (int nt = 0; nt < NTPL; ++nt)
            lg[h][nt] = u[h].x * tt[nt].x + u[h].y * tt[nt].y;

#pragma unroll
    for (int off = 16; off > 0; off >>= 1)
#pragma unroll
        for (int h = 0; h < NH; ++h)
#pragma unroll
            for (int nt = 0; nt < NTPL; ++nt)
                lg[h][nt] += __shfl_xor_sync(0xFFFFFFFFu, lg[h][nt], off);

    float bias[NTPL];
#pragma unroll
    for (int nt = 0; nt < NTPL; ++nt) bias[nt] = 100000.0f * (__ldg(mask + nt) - 1.0f);

    float at[NH][NTPL];
#pragma unroll
    for (int h = 0; h < NH; ++h) {
        float l0 = lg[h][0] + bias[0], l1 = lg[h][1] + bias[1];
        float l2 = lg[h][2] + bias[2], l3 = lg[h][3] + bias[3];
        float mx = fmaxf(fmaxf(l0, l1), fmaxf(l2, l3));
        float e0 = __expf(l0 - mx), e1 = __expf(l1 - mx);
        float e2 = __expf(l2 - mx), e3 = __expf(l3 - mx);
        float inv = __fdividef(1.0f, e0 + e1 + e2 + e3);
        at[h][0] = e0 * inv; at[h][1] = e1 * inv;
        at[h][2] = e2 * inv; at[h][3] = e3 * inv;
    }

#pragma unroll
    for (int h = 0; h < NH; ++h) {
        float mx = at[h][0] * tt[0].x + at[h][1] * tt[1].x +
                   at[h][2] * tt[2].x + at[h][3] * tt[3].x;
        float my = at[h][0] * tt[0].y + at[h][1] * tt[1].y +
                   at[h][2] * tt[2].y + at[h][3] * tt[3].y;
        __nv_bfloat16 hx = __float2bfloat16(mx), hy = __float2bfloat16(my);
        size_t o = (size_t)p * 256 + h * 64 + 2 * l;
        *(uint32_t*)(g_Mh + o) = pack_bf2(mx, my);
        *(uint32_t*)(g_Ml + o) =
            pack_bf2(mx - __bfloat162float(hx), my - __bfloat162float(hy));
    }
}

// ---------------- launch ----------------
extern "C" void kernel_launch(void* const* d_in, const int* in_sizes, int n_in,
                              void* d_out, int out_size) {
    const float* t    = (const float*)d_in[0];
    const float* z    = (const float*)d_in[1];
    const float* mask = (const float*)d_in[2];
    const float* wq   = (const float*)d_in[3];
    const float* wk   = (const float*)d_in[4];
    const float* wv   = (const float*)d_in[5];
    const float* wo   = (const float*)d_in[6];
    const float* bo   = (const float*)d_in[7];
    float* out = (float*)d_out;

    cudaFuncSetAttribute(gemm1_kernel,
                         cudaFuncAttributeMaxDynamicSharedMemorySize, G1SMEM);
    cudaFuncSetAttribute(gemm2_kernel,
                         cudaFuncAttributeMaxDynamicSharedMemorySize, GSMEM);

    // 1. weights precombine + bf16 hi/lo split
    prep_kernel<<<256, 256>>>(wq, wk, wv, wo);

    // 2. U = Z @ Ac (fp32 z in, in-smem hi/lo split; fp32 U out)
    gemm1_kernel<<<dim3(NPIX / 128, 2), 256, G1SMEM>>>(z);

    // 3. attention: U, t, mask -> M (bf16 hi/lo)
    attn_kernel<<<NPIX / 8, 256>>>(t, mask);

    // 4. out = M @ Bc + bo
    gemm2_kernel<<<NPIX / 128, 256, GSMEM>>>(bo, out);
}

// round 12
// speedup vs baseline: 1.3004x; 1.0310x over previous
#include <cuda_runtime.h>
#include <cuda_bf16.h>
#include <cstdint>

#define NPIX (512*512)
#define CZ 128
#define CT 64
#define NTPL 4
#define NH 4
#define DH 32

// ---------------- device scratch ----------------
__device__ __align__(256) float g_U[(size_t)NPIX * 256];           // 256 MB fp32
__device__ __align__(256) __nv_bfloat16 g_Mh[(size_t)NPIX * 256];  // 128 MB
__device__ __align__(256) __nv_bfloat16 g_Ml[(size_t)NPIX * 256];  // 128 MB
// combined weights, bf16 hi/lo, [n][k] row-major
__device__ __align__(256) __nv_bfloat16 g_W1h[2 * 128 * 128];      // [nh][n][kz]
__device__ __align__(256) __nv_bfloat16 g_W1l[2 * 128 * 128];
__device__ __align__(256) __nv_bfloat16 g_W2h[128 * 256];          // [n][kk]
__device__ __align__(256) __nv_bfloat16 g_W2l[128 * 256];

// ---------------- helpers ----------------
__device__ __forceinline__ uint32_t smem_u32(const void* p) {
    uint32_t a;
    asm("{ .reg .u64 t; cvta.to.shared.u64 t, %1; cvt.u32.u64 %0, t; }" : "=r"(a) : "l"(p));
    return a;
}
__device__ __forceinline__ void ldx4(uint32_t r[4], uint32_t addr) {
    asm volatile("ldmatrix.sync.aligned.m8n8.x4.shared.b16 {%0,%1,%2,%3}, [%4];"
                 : "=r"(r[0]), "=r"(r[1]), "=r"(r[2]), "=r"(r[3]) : "r"(addr));
}
__device__ __forceinline__ void mma16816(float c[4], const uint32_t a[4],
                                         uint32_t b0, uint32_t b1) {
    asm volatile(
        "mma.sync.aligned.m16n8k16.row.col.f32.bf16.bf16.f32 "
        "{%0,%1,%2,%3}, {%4,%5,%6,%7}, {%8,%9}, {%0,%1,%2,%3};"
        : "+f"(c[0]), "+f"(c[1]), "+f"(c[2]), "+f"(c[3])
        : "r"(a[0]), "r"(a[1]), "r"(a[2]), "r"(a[3]), "r"(b0), "r"(b1));
}
__device__ __forceinline__ uint32_t pack_bf2(float x, float y) {
    __nv_bfloat162 p = __halves2bfloat162(__float2bfloat16(x), __float2bfloat16(y));
    return *(uint32_t*)&p;
}
__device__ __forceinline__ void cp16(uint32_t dst, const void* src) {
    asm volatile("cp.async.cg.shared.global [%0], [%1], 16;" :: "r"(dst), "l"(src));
}
__device__ __forceinline__ void cp_commit() { asm volatile("cp.async.commit_group;"); }
__device__ __forceinline__ void cp_wait0() {
    asm volatile("cp.async.wait_group 0;" ::: "memory");
}

// ---------------- prep: combined weights, bf16 hi/lo split ----------------
__global__ void prep_kernel(const float* __restrict__ wq, const float* __restrict__ wk,
                            const float* __restrict__ wv, const float* __restrict__ wo) {
    int id = blockIdx.x * blockDim.x + threadIdx.x;
    float val;
    __nv_bfloat16 *dh, *dl;
    int idx;
    if (id < 32768) {
        int kz = id & 127, n = (id >> 7) & 127, nh = id >> 14;
        int hc = nh * 128 + n;
        int h = hc >> 6, c = hc & 63;
        float s = 0.f;
#pragma unroll
        for (int dd = 0; dd < DH; ++dd)
            s += wq[kz * CZ + h * DH + dd] * wk[c * CZ + h * DH + dd];
        val = s * 0.17677669529663687f;
        dh = g_W1h; dl = g_W1l; idx = id;
    } else {
        int e = id - 32768;
        int kk = e & 255, n = e >> 8;
        int h = kk >> 6, c = kk & 63;
        float s = 0.f;
#pragma unroll
        for (int dd = 0; dd < DH; ++dd)
            s += wv[c * CZ + h * DH + dd] * wo[(h * DH + dd) * CZ + n];
        val = s;
        dh = g_W2h; dl = g_W2l; idx = e;
    }
    __nv_bfloat16 hi = __float2bfloat16(val);
    __nv_bfloat16 lo = __float2bfloat16(val - __bfloat162float(hi));
    dh[idx] = hi;
    dl[idx] = lo;
}

// ---------------- shared inner-chunk compute (hoisted B, pipelined A) ----------------
__device__ __forceinline__ void chunk_mma(
    uint32_t aBh, uint32_t aBl, uint32_t wBh, uint32_t wBl, uint32_t kAbase,
    float acc[4][4][4], int lrow, int lkb, int mw, int nw) {
#pragma unroll
    for (int k16 = 0; k16 < 2; ++k16) {
        const uint32_t kb = (uint32_t)(k16 * 32 + lkb);
        // hoist all B fragment loads (4 independent ldx4)
        uint32_t bh[2][4], bl[2][4];
#pragma unroll
        for (int ng = 0; ng < 2; ++ng) {
            uint32_t off = (uint32_t)(nw * 32 + ng * 16 + lrow) * 80 + kb;
            ldx4(bh[ng], wBh + off);
            ldx4(bl[ng], wBl + off);
        }
        // A fragments double-buffered across mb
        uint32_t ah[2][4], al[2][4];
        {
            uint32_t off = (uint32_t)(mw * 64 + lrow) * 80 + kAbase + kb;
            ldx4(ah[0], aBh + off);
            ldx4(al[0], aBl + off);
        }
#pragma unroll
        for (int mb = 0; mb < 4; ++mb) {
            const int cur = mb & 1;
            if (mb < 3) {
                uint32_t off =
                    (uint32_t)(mw * 64 + (mb + 1) * 16 + lrow) * 80 + kAbase + kb;
                ldx4(ah[cur ^ 1], aBh + off);
                ldx4(al[cur ^ 1], aBl + off);
            }
#pragma unroll
            for (int nb = 0; nb < 4; ++nb) {
                const int ng = nb >> 1, hf = nb & 1;
                mma16816(acc[mb][nb], ah[cur], bh[ng][hf], bh[ng][2 + hf]);
                mma16816(acc[mb][nb], ah[cur], bl[ng][hf], bl[ng][2 + hf]);
                mma16816(acc[mb][nb], al[cur], bh[ng][hf], bh[ng][2 + hf]);
            }
        }
    }
}

// ===================== GEMM1: U = Z @ W1, fp32 z in, in-smem split =====================
// CTA 128x128, 256 threads, warps 2(M)x4(N), warp tile 64x32, K=128 (4 chunks of 32).
// smem: Ahi @0 (10240), Alo @10240, W 2stage x 2plane @20480 (40960), zstage @61440 (16384).
static constexpr int G1_AL = 10240;
static constexpr int G1_W = 20480;
static constexpr int G1_STG = 61440;
static constexpr int G1SMEM = 77824;

__global__ __launch_bounds__(256, 2) void gemm1_kernel(const float* __restrict__ z) {
    extern __shared__ char sm[];
    const uint32_t sbase = smem_u32(sm);
    const int tid = threadIdx.x;
    const int lane = tid & 31;
    const int wid = tid >> 5;
    const int mw = wid & 1, nw = wid >> 1;
    const int pb = blockIdx.x * 128;
    const int nh = blockIdx.y;

    const __nv_bfloat16* __restrict__ Wh = g_W1h + nh * 16384;
    const __nv_bfloat16* __restrict__ Wl = g_W1l + nh * 16384;

    auto issue = [&](int kt, int s) {
#pragma unroll
        for (int i = 0; i < 4; ++i) {
            int id = tid + 256 * i;            // 0..1023
            int r = id >> 3, c = id & 7;
            cp16(sbase + (uint32_t)(G1_STG + r * 128 + c * 16),
                 z + (size_t)(pb + r) * 128 + kt * 32 + c * 4);
        }
#pragma unroll
        for (int i = 0; i < 4; ++i) {
            int id = tid + 256 * i;
            int plane = id >> 9;
            int r = (id >> 2) & 127;
            int c = id & 3;
            cp16(sbase + (uint32_t)(G1_W + (s * 2 + plane) * 10240 + r * 80 + c * 16),
                 (plane ? Wl : Wh) + (size_t)r * 128 + kt * 32 + c * 8);
        }
        cp_commit();
    };

    float acc[4][4][4];
#pragma unroll
    for (int i = 0; i < 4; ++i)
#pragma unroll
        for (int j = 0; j < 4; ++j)
#pragma unroll
            for (int q = 0; q < 4; ++q) acc[i][j][q] = 0.f;

    const int lrow = lane & 15;
    const int lkb = (lane >> 4) * 16;

    issue(0, 0);

#pragma unroll
    for (int kt = 0; kt < 4; ++kt) {
        const int s = kt & 1;
        cp_wait0();
        __syncthreads();

        // convert staging fp32 -> hi/lo bf16 A planes
        {
            int r = tid >> 1, half = tid & 1;
            const float4* src = (const float4*)(sm + G1_STG + r * 128 + half * 64);
#pragma unroll
            for (int j = 0; j < 4; ++j) {
                float4 v = src[j];
                __nv_bfloat16 h0 = __float2bfloat16(v.x), h1 = __float2bfloat16(v.y);
                __nv_bfloat16 h2 = __float2bfloat16(v.z), h3 = __float2bfloat16(v.w);
                uint32_t hw0 = pack_bf2(v.x, v.y);
                uint32_t hw1 = pack_bf2(v.z, v.w);
                uint32_t lw0 = pack_bf2(v.x - __bfloat162float(h0),
                                        v.y - __bfloat162float(h1));
                uint32_t lw1 = pack_bf2(v.z - __bfloat162float(h2),
                                        v.w - __bfloat162float(h3));
                uint32_t base = (uint32_t)(r * 80 + half * 32 + j * 8);
                *(uint32_t*)(sm + base) = hw0;
                *(uint32_t*)(sm + base + 4) = hw1;
                *(uint32_t*)(sm + G1_AL + base) = lw0;
                *(uint32_t*)(sm + G1_AL + base + 4) = lw1;
            }
        }
        __syncthreads();

        if (kt < 3) issue(kt + 1, s ^ 1);

        chunk_mma(sbase, sbase + G1_AL,
                  sbase + (uint32_t)(G1_W + s * 2 * 10240),
                  sbase + (uint32_t)(G1_W + s * 2 * 10240 + 10240),
                  0, acc, lrow, lkb, mw, nw);
    }

    // epilogue: fp32 U (stride 256, colbase nh*128)
    const int r4 = lane >> 2, c2 = (lane & 3) * 2;
#pragma unroll
    for (int mb = 0; mb < 4; ++mb)
#pragma unroll
        for (int nb = 0; nb < 4; ++nb) {
            int row = pb + mw * 64 + mb * 16 + r4;
            int col = nh * 128 + nw * 32 + nb * 8 + c2;
            *(float2*)(&g_U[(size_t)row * 256 + col]) =
                make_float2(acc[mb][nb][0], acc[mb][nb][1]);
            *(float2*)(&g_U[(size_t)(row + 8) * 256 + col]) =
                make_float2(acc[mb][nb][2], acc[mb][nb][3]);
        }
}

// ===================== GEMM2: out = M @ Bc + bo =====================
static constexpr int GSMEM = 81920;

__global__ __launch_bounds__(256, 2) void gemm2_kernel(const float* __restrict__ bias,
                                                       float* __restrict__ Cout) {
    extern __shared__ char sm[];
    const uint32_t sbase = smem_u32(sm);
    const int tid = threadIdx.x;
    const int lane = tid & 31;
    const int wid = tid >> 5;
    const int mw = wid & 1, nw = wid >> 1;
    const int pb = blockIdx.x * 128;
    constexpr int KTOT = 256, NC = 8;

    auto issue = [&](int kt, int s) {
#pragma unroll
        for (int i = 0; i < 4; ++i) {
            int id = tid + 256 * i;
            int plane = id >> 9;
            int r = (id >> 2) & 127;
            int c = id & 3;
            const __nv_bfloat16* asrc = (plane ? g_Ml : g_Mh)
                + (size_t)(pb + r) * KTOT + kt * 32 + c * 8;
            cp16(sbase + (uint32_t)((s * 2 + plane) * 10240 + r * 80 + c * 16), asrc);
            const __nv_bfloat16* wsrc = (plane ? g_W2l : g_W2h)
                + (size_t)r * KTOT + kt * 32 + c * 8;
            cp16(sbase + (uint32_t)(40960 + (s * 2 + plane) * 10240 + r * 80 + c * 16), wsrc);
        }
        cp_commit();
    };

    float acc[4][4][4];
#pragma unroll
    for (int i = 0; i < 4; ++i)
#pragma unroll
        for (int j = 0; j < 4; ++j)
#pragma unroll
            for (int q = 0; q < 4; ++q) acc[i][j][q] = 0.f;

    const int lrow = lane & 15;
    const int lkb = (lane >> 4) * 16;

    issue(0, 0);

#pragma unroll
    for (int kt = 0; kt < NC; ++kt) {
        const int s = kt & 1;
        cp_wait0();
        __syncthreads();
        if (kt + 1 < NC) issue(kt + 1, s ^ 1);

        chunk_mma(sbase + (uint32_t)(s * 2) * 10240,
                  sbase + (uint32_t)(s * 2) * 10240 + 10240,
                  sbase + 40960u + (uint32_t)(s * 2) * 10240,
                  sbase + 40960u + (uint32_t)(s * 2) * 10240 + 10240,
                  0, acc, lrow, lkb, mw, nw);
    }

    const int r4 = lane >> 2, c2 = (lane & 3) * 2;
#pragma unroll
    for (int mb = 0; mb < 4; ++mb)
#pragma unroll
        for (int nb = 0; nb < 4; ++nb) {
            int row = pb + mw * 64 + mb * 16 + r4;
            int col = nw * 32 + nb * 8 + c2;
            float2 b = *(const float2*)(bias + col);
            float2 v0 = make_float2(acc[mb][nb][0] + b.x, acc[mb][nb][1] + b.y);
            float2 v1 = make_float2(acc[mb][nb][2] + b.x, acc[mb][nb][3] + b.y);
            *(float2*)(&Cout[(size_t)row * 128 + col]) = v0;
            *(float2*)(&Cout[(size_t)(row + 8) * 128 + col]) = v1;
        }
}

// ---------------- per-pixel attention (warp per pixel), vectorized ----------------
__global__ void attn_kernel(const float* __restrict__ t, const float* __restrict__ mask) {
    int p = blockIdx.x * 8 + (threadIdx.x >> 5);
    int l = threadIdx.x & 31;

    float2 u[NH];
#pragma unroll
    for (int h = 0; h < NH; ++h)
        u[h] = *(const float2*)(g_U + (size_t)p * 256 + h * 64 + 2 * l);

    float2 tt[NTPL];
#pragma unroll
    for (int nt = 0; nt < NTPL; ++nt)
        tt[nt] = *(const float2*)(t + ((size_t)nt * NPIX + p) * CT + 2 * l);

    float lg[NH][NTPL];
#pragma unroll
    for (int h = 0; h < NH; ++h)
#pragma unroll
        for (int nt = 0; nt < NTPL; ++nt)
            lg[h][nt] = u[h].x * tt[nt].x + u[h].y * tt[nt].y;

#pragma unroll
    for (int off = 16; off > 0; off >>= 1)
#pragma unroll
        for (int h = 0; h < NH; ++h)
#pragma unroll
            for (int nt = 0; nt < NTPL; ++nt)
                lg[h][nt] += __shfl_xor_sync(0xFFFFFFFFu, lg[h][nt], off);

    float bias[NTPL];
#pragma unroll
    for (int nt = 0; nt < NTPL; ++nt) bias[nt] = 100000.0f * (__ldg(mask + nt) - 1.0f);

    float at[NH][NTPL];
#pragma unroll
    for (int h = 0; h < NH; ++h) {
        float l0 = lg[h][0] + bias[0], l1 = lg[h][1] + bias[1];
        float l2 = lg[h][2] + bias[2], l3 = lg[h][3] + bias[3];
        float mx = fmaxf(fmaxf(l0, l1), fmaxf(l2, l3));
        float e0 = __expf(l0 - mx), e1 = __expf(l1 - mx);
        float e2 = __expf(l2 - mx), e3 = __expf(l3 - mx);
        float inv = __fdividef(1.0f, e0 + e1 + e2 + e3);
        at[h][0] = e0 * inv; at[h][1] = e1 * inv;
        at[h][2] = e2 * inv; at[h][3] = e3 * inv;
    }

#pragma unroll
    for (int h = 0; h < NH; ++h) {
        float mx = at[h][0] * tt[0].x + at[h][1] * tt[1].x +
                   at[h][2] * tt[2].x + at[h][3] * tt[3].x;
        float my = at[h][0] * tt[0].y + at[h][1] * tt[1].y +
                   at[h][2] * tt[2].y + at[h][3] * tt[3].y;
        __nv_bfloat16 hx = __float2bfloat16(mx), hy = __float2bfloat16(my);
        size_t o = (size_t)p * 256 + h * 64 + 2 * l;
        *(uint32_t*)(g_Mh + o) = pack_bf2(mx, my);
        *(uint32_t*)(g_Ml + o) =
            pack_bf2(mx - __bfloat162float(hx), my - __bfloat162float(hy));
    }
}

// ---------------- launch ----------------
extern "C" void kernel_launch(void* const* d_in, const int* in_sizes, int n_in,
                              void* d_out, int out_size) {
    const float* t    = (const float*)d_in[0];
    const float* z    = (const float*)d_in[1];
    const float* mask = (const float*)d_in[2];
    const float* wq   = (const float*)d_in[3];
    const float* wk   = (const float*)d_in[4];
    const float* wv   = (const float*)d_in[5];
    const float* wo   = (const float*)d_in[6];
    const float* bo   = (const float*)d_in[7];
    float* out = (float*)d_out;

    cudaFuncSetAttribute(gemm1_kernel,
                         cudaFuncAttributeMaxDynamicSharedMemorySize, G1SMEM);
    cudaFuncSetAttribute(gemm2_kernel,
                         cudaFuncAttributeMaxDynamicSharedMemorySize, GSMEM);

    // 1. weights precombine + bf16 hi/lo split
    prep_kernel<<<256, 256>>>(wq, wk, wv, wo);

    // 2. U = Z @ Ac (fp32 z in, in-smem hi/lo split; fp32 U out)
    gemm1_kernel<<<dim3(NPIX / 128, 2), 256, G1SMEM>>>(z);

    // 3. attention: U, t, mask -> M (bf16 hi/lo)
    attn_kernel<<<NPIX / 8, 256>>>(t, mask);

    // 4. out = M @ Bc + bo
    gemm2_kernel<<<NPIX / 128, 256, GSMEM>>>(bo, out);
}